// round 3
// baseline (speedup 1.0000x reference)
#include <cuda_runtime.h>

// RNN forward, fused persistent kernel. B=256, T=1024, IN=4, H=256, OUT=1.
// 128 CTAs x 256 threads; CTA = 2 batches.
// Single __syncthreads per step: each warp redundantly reduces the k-slice of h
// it needs (double-buffered partials), stores to a warp-private hbuf, then runs
// its FFMA2 phase. Wh: 80 u64-pairs/thread in regs + 24 ulonglong2 from smem.

typedef unsigned long long u64;

#define T_LEN   1024

__device__ __forceinline__ u64 ffma2(u64 a, u64 b, u64 c) {
    u64 d;
    asm("fma.rn.f32x2 %0, %1, %2, %3;" : "=l"(d) : "l"(a), "l"(b), "l"(c));
    return d;
}
__device__ __forceinline__ float lo32(u64 v) { return __uint_as_float((unsigned)(v & 0xffffffffu)); }
__device__ __forceinline__ float hi32(u64 v) { return __uint_as_float((unsigned)(v >> 32)); }

__device__ __forceinline__ float fast_tanh(float x) {
    float a = fabsf(x);
    float e = __expf(2.0f * a);
    float r = 1.0f - __fdividef(2.0f, e + 1.0f);
    return copysignf(r, x);
}

// shared memory byte offsets
#define SM_WHS   0                  // ulonglong2 WHS[8][24][32]     = 98304 B
#define SM_PART  98304              // float part[2][8][256]         = 16384 B
#define SM_HBUF  114688             // float hbuf[8][2][64]          = 4096 B
#define SM_XS    118784             // float xs[2][2][4]             = 64 B
#define SM_SCR   118848             // float scratch[16]             = 64 B
#define SM_TOTAL 118912

__global__ void __launch_bounds__(256, 1)
rnn_kernel(const float* __restrict__ x,        // [256][1024][4]
           const float* __restrict__ W_i2h,    // [256][260]  (cols 0..3 = Wx, 4..259 = Wh)
           const float* __restrict__ b_i2h,    // [256]
           const float* __restrict__ W_h2o,    // [256]
           const float* __restrict__ b_h2o,    // [1]
           const float* __restrict__ init_h,   // [256]
           float* __restrict__ out)            // [256]
{
    extern __shared__ unsigned char sm[];
    ulonglong2* WHS = (ulonglong2*)(sm + SM_WHS);
    float* part = (float*)(sm + SM_PART);       // part[buf][kgp*2+b][h]
    float* hbuf = (float*)(sm + SM_HBUF);       // hbuf[w][b][64]
    float* xs   = (float*)(sm + SM_XS);         // xs[buf][b][4]
    float* scratch = (float*)(sm + SM_SCR);

    const int t  = threadIdx.x;
    const int w  = t >> 5;
    const int l  = t & 31;
    const int kg = w & 3;             // k-group: k in [64*kg, 64*kg+64)
    const int hg = w >> 2;            // h-group for FMA partial rows
    const int kbase = kg * 64;

    const int b0 = blockIdx.x * 2;
    const int h0r = hg * 128 + l;     // + i*32, i=0..3: this thread's 4 FMA h-rows

    // ---- Wh split: rows 0,1 + row2 pairs 0..15 in regs (80 u64 pairs);
    //      row2 pairs 16..31 (8 ull2) + row3 (16 ull2) in smem: 24 ull2/thread ----
    u64 wreg[80];
    {
        #pragma unroll
        for (int i = 0; i < 2; i++) {
            const ulonglong2* rp = (const ulonglong2*)(W_i2h + (size_t)(h0r + i*32) * 260 + 4 + kbase);
            #pragma unroll
            for (int jj = 0; jj < 16; jj++) {
                ulonglong2 v = rp[jj];
                wreg[i*32 + 2*jj]     = v.x;
                wreg[i*32 + 2*jj + 1] = v.y;
            }
        }
        const ulonglong2* rp2 = (const ulonglong2*)(W_i2h + (size_t)(h0r + 2*32) * 260 + 4 + kbase);
        #pragma unroll
        for (int jj = 0; jj < 8; jj++) {
            ulonglong2 v = rp2[jj];
            wreg[64 + 2*jj]     = v.x;
            wreg[64 + 2*jj + 1] = v.y;
        }
        #pragma unroll
        for (int jj = 8; jj < 16; jj++)
            WHS[(w*24 + (jj - 8))*32 + l] = rp2[jj];
        const ulonglong2* rp3 = (const ulonglong2*)(W_i2h + (size_t)(h0r + 3*32) * 260 + 4 + kbase);
        #pragma unroll
        for (int jj = 0; jj < 16; jj++)
            WHS[(w*24 + 8 + jj)*32 + l] = rp3[jj];
    }

    // ---- reducer-role preloads for this lane's two h indices in kg slice ----
    const int hh0 = kbase + l;
    const int hh1 = kbase + 32 + l;
    const float4 wxA = *(const float4*)(W_i2h + (size_t)hh0 * 260);
    const float4 wxB = *(const float4*)(W_i2h + (size_t)hh1 * 260);
    const float biA = b_i2h[hh0];
    const float biB = b_i2h[hh1];
    const float woA = W_h2o[hh0];
    const float woB = W_h2o[hh1];
    const float bo  = b_h2o[0];

    float* myhb = hbuf + w * 128;     // [b][64]

    // ---- prologue: h_{-1} = init_h; run FMA phase once to fill part[0]; stage x_0 ----
    {
        float hA = init_h[hh0];
        float hB = init_h[hh1];
        myhb[0*64 + l]      = hA;
        myhb[0*64 + 32 + l] = hB;
        myhb[1*64 + l]      = hA;
        myhb[1*64 + 32 + l] = hB;
        if (t < 2) {
            float4 xv = *(const float4*)(x + ((size_t)(b0 + t) * T_LEN + 0) * 4);
            *(float4*)(xs + t*4) = xv;
        }
    }
    __syncwarp();

    float pool0a = 0.f, pool0b = 0.f, pool1a = 0.f, pool1b = 0.f;

    // FMA phase as a lambda-ish macro via a loop body; prologue writes part[0]
    {
        const ulonglong2* hp0 = (const ulonglong2*)(myhb);
        const ulonglong2* hp1 = (const ulonglong2*)(myhb + 64);
        u64 acc[4][2];
        #pragma unroll
        for (int i = 0; i < 4; i++) { acc[i][0] = 0ULL; acc[i][1] = 0ULL; }
        #pragma unroll
        for (int jj = 0; jj < 16; jj++) {
            ulonglong2 h0v = hp0[jj];
            ulonglong2 h1v = hp1[jj];
            #pragma unroll
            for (int i = 0; i < 2; i++) {
                u64 wa = wreg[i*32 + 2*jj];
                u64 wb = wreg[i*32 + 2*jj + 1];
                acc[i][0] = ffma2(wa, h0v.x, acc[i][0]);
                acc[i][0] = ffma2(wb, h0v.y, acc[i][0]);
                acc[i][1] = ffma2(wa, h1v.x, acc[i][1]);
                acc[i][1] = ffma2(wb, h1v.y, acc[i][1]);
            }
            u64 wa2, wb2;
            if (jj < 8) { wa2 = wreg[64 + 2*jj]; wb2 = wreg[64 + 2*jj + 1]; }
            else { ulonglong2 v = WHS[(w*24 + (jj - 8))*32 + l]; wa2 = v.x; wb2 = v.y; }
            acc[2][0] = ffma2(wa2, h0v.x, acc[2][0]);
            acc[2][0] = ffma2(wb2, h0v.y, acc[2][0]);
            acc[2][1] = ffma2(wa2, h1v.x, acc[2][1]);
            acc[2][1] = ffma2(wb2, h1v.y, acc[2][1]);
            ulonglong2 v3 = WHS[(w*24 + 8 + jj)*32 + l];
            acc[3][0] = ffma2(v3.x, h0v.x, acc[3][0]);
            acc[3][0] = ffma2(v3.y, h0v.y, acc[3][0]);
            acc[3][1] = ffma2(v3.x, h1v.x, acc[3][1]);
            acc[3][1] = ffma2(v3.y, h1v.y, acc[3][1]);
        }
        #pragma unroll
        for (int i = 0; i < 4; i++) {
            int hh = h0r + i*32;
            part[(0*8 + kg*2 + 0)*256 + hh] = lo32(acc[i][0]) + hi32(acc[i][0]);
            part[(0*8 + kg*2 + 1)*256 + hh] = lo32(acc[i][1]) + hi32(acc[i][1]);
        }
    }
    __syncthreads();

    const bool owner = (w < 4);

    for (int step = 0; step < T_LEN; step++) {
        const int cur = step & 1;
        const int nxt = cur ^ 1;
        const float* pc = part + cur * 8 * 256;

        // ---- reduce this warp's k-slice: 4 items (b,hh) per lane ----
        float r00 = pc[(0*2+0)*256 + hh0] + pc[(1*2+0)*256 + hh0]
                  + pc[(2*2+0)*256 + hh0] + pc[(3*2+0)*256 + hh0];
        float r01 = pc[(0*2+0)*256 + hh1] + pc[(1*2+0)*256 + hh1]
                  + pc[(2*2+0)*256 + hh1] + pc[(3*2+0)*256 + hh1];
        float r10 = pc[(0*2+1)*256 + hh0] + pc[(1*2+1)*256 + hh0]
                  + pc[(2*2+1)*256 + hh0] + pc[(3*2+1)*256 + hh0];
        float r11 = pc[(0*2+1)*256 + hh1] + pc[(1*2+1)*256 + hh1]
                  + pc[(2*2+1)*256 + hh1] + pc[(3*2+1)*256 + hh1];

        const float* x0 = xs + cur*8;
        float xp00 = biA + wxA.x*x0[0] + wxA.y*x0[1] + wxA.z*x0[2] + wxA.w*x0[3];
        float xp01 = biB + wxB.x*x0[0] + wxB.y*x0[1] + wxB.z*x0[2] + wxB.w*x0[3];
        float xp10 = biA + wxA.x*x0[4] + wxA.y*x0[5] + wxA.z*x0[6] + wxA.w*x0[7];
        float xp11 = biB + wxB.x*x0[4] + wxB.y*x0[5] + wxB.z*x0[6] + wxB.w*x0[7];

        float h00 = fast_tanh(xp00 + r00);
        float h01 = fast_tanh(xp01 + r01);
        float h10 = fast_tanh(xp10 + r10);
        float h11 = fast_tanh(xp11 + r11);

        if (owner) { pool0a += h00; pool0b += h01; pool1a += h10; pool1b += h11; }

        myhb[0*64 + l]      = h00;
        myhb[0*64 + 32 + l] = h01;
        myhb[1*64 + l]      = h10;
        myhb[1*64 + 32 + l] = h11;

        // stage x for next step
        if (t < 2) {
            int tn = (step < T_LEN - 1) ? (step + 1) : step;
            float4 xv = *(const float4*)(x + ((size_t)(b0 + t) * T_LEN + tn) * 4);
            *(float4*)(xs + nxt*8 + t*4) = xv;
        }
        __syncwarp();

        // ---- FMA phase (skip on last step: result unused) ----
        if (step < T_LEN - 1) {
            const ulonglong2* hp0 = (const ulonglong2*)(myhb);
            const ulonglong2* hp1 = (const ulonglong2*)(myhb + 64);
            u64 acc[4][2];
            #pragma unroll
            for (int i = 0; i < 4; i++) { acc[i][0] = 0ULL; acc[i][1] = 0ULL; }
            #pragma unroll
            for (int jj = 0; jj < 16; jj++) {
                ulonglong2 h0v = hp0[jj];
                ulonglong2 h1v = hp1[jj];
                #pragma unroll
                for (int i = 0; i < 2; i++) {
                    u64 wa = wreg[i*32 + 2*jj];
                    u64 wb = wreg[i*32 + 2*jj + 1];
                    acc[i][0] = ffma2(wa, h0v.x, acc[i][0]);
                    acc[i][0] = ffma2(wb, h0v.y, acc[i][0]);
                    acc[i][1] = ffma2(wa, h1v.x, acc[i][1]);
                    acc[i][1] = ffma2(wb, h1v.y, acc[i][1]);
                }
                u64 wa2, wb2;
                if (jj < 8) { wa2 = wreg[64 + 2*jj]; wb2 = wreg[64 + 2*jj + 1]; }
                else { ulonglong2 v = WHS[(w*24 + (jj - 8))*32 + l]; wa2 = v.x; wb2 = v.y; }
                acc[2][0] = ffma2(wa2, h0v.x, acc[2][0]);
                acc[2][0] = ffma2(wb2, h0v.y, acc[2][0]);
                acc[2][1] = ffma2(wa2, h1v.x, acc[2][1]);
                acc[2][1] = ffma2(wb2, h1v.y, acc[2][1]);
                ulonglong2 v3 = WHS[(w*24 + 8 + jj)*32 + l];
                acc[3][0] = ffma2(v3.x, h0v.x, acc[3][0]);
                acc[3][0] = ffma2(v3.y, h0v.y, acc[3][0]);
                acc[3][1] = ffma2(v3.x, h1v.x, acc[3][1]);
                acc[3][1] = ffma2(v3.y, h1v.y, acc[3][1]);
            }
            float* pn = part + nxt * 8 * 256;
            #pragma unroll
            for (int i = 0; i < 4; i++) {
                int hh = h0r + i*32;
                pn[(kg*2 + 0)*256 + hh] = lo32(acc[i][0]) + hi32(acc[i][0]);
                pn[(kg*2 + 1)*256 + hh] = lo32(acc[i][1]) + hi32(acc[i][1]);
            }
        }
        __syncthreads();
    }

    // ---- output head: out[b] = (1/1024) * sum_h pool[h]*wo[h] + bo ----
    if (owner) {
        float v0 = pool0a * woA + pool0b * woB;
        float v1 = pool1a * woA + pool1b * woB;
        #pragma unroll
        for (int o = 16; o > 0; o >>= 1) {
            v0 += __shfl_down_sync(0xffffffffu, v0, o);
            v1 += __shfl_down_sync(0xffffffffu, v1, o);
        }
        if (l == 0) { scratch[w] = v0; scratch[8 + w] = v1; }
    }
    __syncthreads();
    if (t == 0) {
        float s = scratch[0] + scratch[1] + scratch[2] + scratch[3];
        out[b0] = s * (1.0f / 1024.0f) + bo;
    } else if (t == 1) {
        float s = scratch[8] + scratch[9] + scratch[10] + scratch[11];
        out[b0 + 1] = s * (1.0f / 1024.0f) + bo;
    }
}

extern "C" void kernel_launch(void* const* d_in, const int* in_sizes, int n_in,
                              void* d_out, int out_size) {
    const float* x     = (const float*)d_in[0];
    const float* W_i2h = (const float*)d_in[1];
    const float* b_i2h = (const float*)d_in[2];
    const float* W_h2o = (const float*)d_in[3];
    const float* b_h2o = (const float*)d_in[4];
    const float* ih    = (const float*)d_in[5];
    float* outp = (float*)d_out;

    cudaFuncSetAttribute(rnn_kernel, cudaFuncAttributeMaxDynamicSharedMemorySize, SM_TOTAL);
    rnn_kernel<<<128, 256, SM_TOTAL>>>(x, W_i2h, b_i2h, W_h2o, b_h2o, ih, outp);
}

// round 4
// speedup vs baseline: 1.0407x; 1.0407x over previous
#include <cuda_runtime.h>

// RNN forward, fused persistent kernel. B=256, T=1024, IN=4, H=256, OUT=1.
// 128 CTAs x 256 threads; CTA = 2 batches for all 1024 steps.
// R1 champion structure: Wh 88 u64-pairs/thread in regs + 20 ulonglong2 from smem,
// FFMA2 inner product, shared reduce (h = threadIdx), double-buffered hbuf.
// R4 deltas: branchless tanh, split phase-A barrier, short x live range.

typedef unsigned long long u64;

#define T_LEN   1024
#define KG_LEN  64

__device__ __forceinline__ u64 ffma2(u64 a, u64 b, u64 c) {
    u64 d;
    asm("fma.rn.f32x2 %0, %1, %2, %3;" : "=l"(d) : "l"(a), "l"(b), "l"(c));
    return d;
}
__device__ __forceinline__ float lo32(u64 v) { return __uint_as_float((unsigned)(v & 0xffffffffu)); }
__device__ __forceinline__ float hi32(u64 v) { return __uint_as_float((unsigned)(v >> 32)); }

__device__ __forceinline__ float fast_tanh(float x) {
    float a = fabsf(x);
    float e = __expf(2.0f * a);
    float r = 1.0f - __fdividef(2.0f, e + 1.0f);
    return copysignf(r, x);
}

// shared memory byte offsets
#define SM_WHS   0                  // ulonglong2 WHS[8][20][32]   = 81920 B
#define SM_HBUF  81920              // float hbuf[2][2][256]       = 4096 B
#define SM_PART  86016              // float part[8][256]          = 8192 B
#define SM_XS    94208              // float xs[2][8]              = 64 B
#define SM_TOTAL 94272

__global__ void __launch_bounds__(256, 1)
rnn_kernel(const float* __restrict__ x,        // [256][1024][4]
           const float* __restrict__ W_i2h,    // [256][260]  (cols 0..3 = Wx, 4..259 = Wh)
           const float* __restrict__ b_i2h,    // [256]
           const float* __restrict__ W_h2o,    // [256]
           const float* __restrict__ b_h2o,    // [1]
           const float* __restrict__ init_h,   // [256]
           float* __restrict__ out)            // [256]
{
    extern __shared__ unsigned char sm[];
    ulonglong2* WHS = (ulonglong2*)(sm + SM_WHS);
    float* hbuf = (float*)(sm + SM_HBUF);
    float* part = (float*)(sm + SM_PART);
    float* xs   = (float*)(sm + SM_XS);

    const int t  = threadIdx.x;
    const int w  = t >> 5;
    const int l  = t & 31;
    const int kg = w & 3;             // k-group: k in [64*kg, 64*kg+64)
    const int hg = w >> 2;            // h-group: h in [128*hg, 128*hg+128)
    const int kbase = kg * KG_LEN;

    const int b0 = blockIdx.x * 2;
    const int h0r = hg * 128 + l;     // + i*32, i=0..3: this thread's 4 h-rows

    // ---- Wh: rows 0,1 + first 24 pairs of row 2 in registers (88 pairs = 176 regs);
    //      rest of row 2 + all of row 3 in smem (20 ulonglong2 per thread = 80KB/CTA) ----
    u64 wreg[88];
    {
        #pragma unroll
        for (int i = 0; i < 2; i++) {
            const ulonglong2* rp = (const ulonglong2*)(W_i2h + (size_t)(h0r + i*32) * 260 + 4 + kbase);
            #pragma unroll
            for (int jj = 0; jj < 16; jj++) {
                ulonglong2 v = rp[jj];
                wreg[i*32 + 2*jj]     = v.x;
                wreg[i*32 + 2*jj + 1] = v.y;
            }
        }
        const ulonglong2* rp2 = (const ulonglong2*)(W_i2h + (size_t)(h0r + 2*32) * 260 + 4 + kbase);
        #pragma unroll
        for (int jj = 0; jj < 12; jj++) {
            ulonglong2 v = rp2[jj];
            wreg[64 + 2*jj]     = v.x;
            wreg[64 + 2*jj + 1] = v.y;
        }
        #pragma unroll
        for (int jj = 12; jj < 16; jj++)
            WHS[(w*20 + (jj - 12))*32 + l] = rp2[jj];
        const ulonglong2* rp3 = (const ulonglong2*)(W_i2h + (size_t)(h0r + 3*32) * 260 + 4 + kbase);
        #pragma unroll
        for (int jj = 0; jj < 16; jj++)
            WHS[(w*20 + 4 + jj)*32 + l] = rp3[jj];
    }

    // reducer-role parameters for h = t
    const float4 wx = *(const float4*)(W_i2h + (size_t)t * 260);   // Wx[t][0..3]
    const float bi = b_i2h[t];

    // init hidden state (buffer 0) and x for step 0
    {
        float hv = init_h[t];
        hbuf[0*512 + 0*256 + t] = hv;
        hbuf[0*512 + 1*256 + t] = hv;
        if (t < 2) {
            float4 xv = *(const float4*)(x + ((size_t)(b0 + t) * T_LEN + 0) * 4);
            *(float4*)(xs + t*4) = xv;
        }
    }
    __syncthreads();

    float pool0 = 0.0f, pool1 = 0.0f;
    int cur = 0;

    for (int step = 0; step < T_LEN; step++) {
        const int nxt = cur ^ 1;

        // ---- FMA phase: partial dot products over this warp's k range ----
        const ulonglong2* hp0 = (const ulonglong2*)(hbuf + cur*512 + 0*256 + kbase);
        const ulonglong2* hp1 = (const ulonglong2*)(hbuf + cur*512 + 1*256 + kbase);

        u64 acc[4][2];
        #pragma unroll
        for (int i = 0; i < 4; i++) { acc[i][0] = 0ULL; acc[i][1] = 0ULL; }

        #pragma unroll
        for (int jj = 0; jj < 16; jj++) {
            ulonglong2 h0v = hp0[jj];
            ulonglong2 h1v = hp1[jj];
            #pragma unroll
            for (int i = 0; i < 2; i++) {
                u64 wa = wreg[i*32 + 2*jj];
                u64 wb = wreg[i*32 + 2*jj + 1];
                acc[i][0] = ffma2(wa, h0v.x, acc[i][0]);
                acc[i][0] = ffma2(wb, h0v.y, acc[i][0]);
                acc[i][1] = ffma2(wa, h1v.x, acc[i][1]);
                acc[i][1] = ffma2(wb, h1v.y, acc[i][1]);
            }
            u64 wa2, wb2;
            if (jj < 12) { wa2 = wreg[64 + 2*jj]; wb2 = wreg[64 + 2*jj + 1]; }
            else { ulonglong2 v = WHS[(w*20 + (jj - 12))*32 + l]; wa2 = v.x; wb2 = v.y; }
            acc[2][0] = ffma2(wa2, h0v.x, acc[2][0]);
            acc[2][0] = ffma2(wb2, h0v.y, acc[2][0]);
            acc[2][1] = ffma2(wa2, h1v.x, acc[2][1]);
            acc[2][1] = ffma2(wb2, h1v.y, acc[2][1]);
            ulonglong2 v3 = WHS[(w*20 + 4 + jj)*32 + l];
            acc[3][0] = ffma2(v3.x, h0v.x, acc[3][0]);
            acc[3][0] = ffma2(v3.y, h0v.y, acc[3][0]);
            acc[3][1] = ffma2(v3.x, h1v.x, acc[3][1]);
            acc[3][1] = ffma2(v3.y, h1v.y, acc[3][1]);
        }

        // write partial sums: part[kg*2+b][h]
        #pragma unroll
        for (int i = 0; i < 4; i++) {
            int hh = h0r + i*32;
            part[(kg*2 + 0)*256 + hh] = lo32(acc[i][0]) + hi32(acc[i][0]);
            part[(kg*2 + 1)*256 + hh] = lo32(acc[i][1]) + hi32(acc[i][1]);
        }

        // stage x for next step now (short live range; xs double-buffered)
        if (t < 2) {
            int tn = (step < T_LEN - 1) ? (step + 1) : step;
            float4 xv = *(const float4*)(x + ((size_t)(b0 + t) * T_LEN + tn) * 4);
            *(float4*)(xs + nxt*8 + t*4) = xv;
        }

        // phase-A barrier: each hg-half (warps 0-3 / 4-7) is a closed
        // producer/consumer set for its 128 h-rows of partials
        if (w < 4) asm volatile("bar.sync 1, 128;" ::: "memory");
        else       asm volatile("bar.sync 2, 128;" ::: "memory");

        // ---- reduce across the 4 k-groups for h = t, tanh, pool, store state ----
        float r0 = (part[0*256 + t] + part[2*256 + t]) +
                   (part[4*256 + t] + part[6*256 + t]);
        float r1 = (part[1*256 + t] + part[3*256 + t]) +
                   (part[5*256 + t] + part[7*256 + t]);
        const float* xsc = xs + cur*8;
        float xp0 = bi + wx.x*xsc[0] + wx.y*xsc[1] + wx.z*xsc[2] + wx.w*xsc[3];
        float xp1 = bi + wx.x*xsc[4] + wx.y*xsc[5] + wx.z*xsc[6] + wx.w*xsc[7];
        float hn0 = fast_tanh(xp0 + r0);
        float hn1 = fast_tanh(xp1 + r1);
        pool0 += hn0;
        pool1 += hn1;
        hbuf[nxt*512 + 0*256 + t] = hn0;
        hbuf[nxt*512 + 1*256 + t] = hn1;
        __syncthreads();
        cur = nxt;
    }

    // ---- output head: out[b] = mean_t(h)[b] . W_h2o + b_h2o ----
    const float wo = W_h2o[t];
    const float bo = b_h2o[0];
    float v0 = pool0 * (1.0f / 1024.0f) * wo;
    float v1 = pool1 * (1.0f / 1024.0f) * wo;
    #pragma unroll
    for (int o = 16; o > 0; o >>= 1) {
        v0 += __shfl_down_sync(0xffffffffu, v0, o);
        v1 += __shfl_down_sync(0xffffffffu, v1, o);
    }
    if (l == 0) { part[w] = v0; part[8 + w] = v1; }
    __syncthreads();
    if (t == 0) {
        float s = 0.0f;
        #pragma unroll
        for (int i = 0; i < 8; i++) s += part[i];
        out[b0] = s + bo;
    } else if (t == 1) {
        float s = 0.0f;
        #pragma unroll
        for (int i = 0; i < 8; i++) s += part[8 + i];
        out[b0 + 1] = s + bo;
    }
}

extern "C" void kernel_launch(void* const* d_in, const int* in_sizes, int n_in,
                              void* d_out, int out_size) {
    const float* x     = (const float*)d_in[0];
    const float* W_i2h = (const float*)d_in[1];
    const float* b_i2h = (const float*)d_in[2];
    const float* W_h2o = (const float*)d_in[3];
    const float* b_h2o = (const float*)d_in[4];
    const float* ih    = (const float*)d_in[5];
    float* outp = (float*)d_out;

    cudaFuncSetAttribute(rnn_kernel, cudaFuncAttributeMaxDynamicSharedMemorySize, SM_TOTAL);
    rnn_kernel<<<128, 256, SM_TOTAL>>>(x, W_i2h, b_i2h, W_h2o, b_h2o, ih, outp);
}